// round 2
// baseline (speedup 1.0000x reference)
#include <cuda_runtime.h>
#include <math.h>

#define Bc 8
#define Sc 96
#define Tc 96
#define Fc 64
#define Hc 64
#define H2 128
#define TILE 8
#define TG 12       // 96 / TILE
#define NDIAG 23    // 2*TG - 1

// Unmasked recurrence state (scratch): needed for halos + depth-1 projections.
__device__ float g_hx[2][Bc][Sc][Tc][Hc];
__device__ float g_hy[2][Bc][Sc][Tc][Hc];
// Depth-0 input projections: px depends only on (b,i), py only on (b,j).
__device__ float g_px0[Bc][Sc][Hc];
__device__ float g_py0[Bc][Tc][Hc];

// ---------------------------------------------------------------------------
// Depth-0 projections: g_px0[b][i][:] = src[b,i,:] @ Wi_x[0];  g_py0 likewise.
// ---------------------------------------------------------------------------
__global__ void proj0_kernel(const float* __restrict__ src,
                             const float* __restrict__ trg,
                             const float* __restrict__ Wix,
                             const float* __restrict__ Wiy)
{
    __shared__ float row[Fc];
    const int r = blockIdx.x;
    const int k = threadIdx.x;
    const float* W;
    const float* inrow;
    float* outp;
    if (r < Bc * Sc) {
        inrow = src + r * Fc;  W = Wix;  outp = &g_px0[0][0][0] + r * Hc;
    } else {
        int rr = r - Bc * Sc;
        inrow = trg + rr * Fc; W = Wiy;  outp = &g_py0[0][0][0] + rr * Hc;
    }
    row[k] = inrow[k];
    __syncthreads();
    float acc = 0.f;
#pragma unroll 8
    for (int f = 0; f < Fc; f++) acc += row[f] * W[f * Hc + k];
    outp[k] = acc;
}

// ---------------------------------------------------------------------------
// Wavefront tile kernel. One CTA = one (depth, tile, batch). Processes the
// 8x8 cell tile with an internal anti-diagonal wavefront.
// ---------------------------------------------------------------------------
#define SMEM_FLOATS (16384 + 8192 + 1024 + 1024 + 512 + 512)
#define SMEM_BYTES  (SMEM_FLOATS * 4)

__global__ void __launch_bounds__(256, 2) wave_kernel(
    const float* __restrict__ Whx, const float* __restrict__ Why,
    const float* __restrict__ bx,  const float* __restrict__ by,
    const float* __restrict__ Wix, const float* __restrict__ Wiy,
    const int*   __restrict__ slen, const int* __restrict__ tlen,
    float* __restrict__ out, int s, int n0)
{
    extern __shared__ float smem[];
    float* Wsh    = smem;           // [128][128]  combined [Whx | Why], row = kk
    float* P      = smem + 16384;   // [64][128]   per-cell input proj (+bias)
    float* HX     = P + 8192;       // [2][8][64]  ping-pong hx along diag
    float* HY     = HX + 1024;      // [2][8][64]
    float* HXtop  = HY + 1024;      // [8][64]     hx halo from tile above (per jj)
    float* HYleft = HXtop + 512;    // [8][64]     hy halo from tile left  (per ii)

    const int t    = threadIdx.x;
    const int slot = blockIdx.x >> 3;
    const int b    = blockIdx.x & 7;

    int depth, diag, pos;
    if (slot < n0) { depth = 0; diag = s;     pos = slot; }
    else           { depth = 1; diag = s - 1; pos = slot - n0; }
    int lo = diag - (TG - 1); if (lo < 0) lo = 0;
    const int ti = lo + pos;
    const int tj = diag - ti;
    const int i0 = ti * TILE, j0 = tj * TILE;

    // ---- load combined recurrence weights [128][128] into shared ----
    {
        const float* WhxD = Whx + depth * H2 * Hc;
        const float* WhyD = Why + depth * H2 * Hc;
        for (int idx = t; idx < H2 * H2; idx += 256) {
            int kk = idx >> 7, k = idx & 127;
            Wsh[idx] = (k < Hc) ? WhxD[kk * Hc + k] : WhyD[kk * Hc + (k - Hc)];
        }
    }

    // ---- halos from neighbor tiles (unmasked scratch), zeros at grid border ----
    for (int idx = t; idx < TILE * Hc; idx += 256) {
        int rr = idx >> 6, k = idx & 63;
        HXtop[idx]  = (ti > 0) ? g_hx[depth][b][i0 - 1][j0 + rr][k] : 0.f;
        HYleft[idx] = (tj > 0) ? g_hy[depth][b][i0 + rr][j0 - 1][k] : 0.f;
    }

    // ---- per-cell input projections P[cell][k] with bias folded in ----
    if (depth == 0) {
        for (int idx = t; idx < 64 * H2; idx += 256) {
            int c = idx >> 7, k = idx & 127;
            int ii = c >> 3, jj = c & 7;
            float v;
            if (k < Hc) v = g_px0[b][i0 + ii][k] + bx[k];
            else        v = g_py0[b][j0 + jj][k - Hc] + by[k - Hc];
            P[idx] = v;
        }
    } else {
        // P[c][k<64]  = hx0(cell) @ Wi_x[1] + b_x[1]
        // P[c][k>=64] = hy0(cell) @ Wi_y[1] + b_y[1]
        const int g  = t >> 5;         // 0..7
        const int kq = t & 31;         // 0..31
        const int k0 = kq * 4;         // 0..124
        const bool px_half = (k0 < Hc);
        const float* Wp = px_half ? (Wix + Hc * Hc + k0)
                                  : (Wiy + Hc * Hc + (k0 - Hc));
        const float4 bv = px_half ? *(const float4*)(bx + Hc + k0)
                                  : *(const float4*)(by + Hc + (k0 - Hc));
        for (int rep = 0; rep < 8; rep++) {
            int c = rep * 8 + g;
            int ii = c >> 3, jj = c & 7;
            const float* h = px_half ? &g_hx[0][b][i0 + ii][j0 + jj][0]
                                     : &g_hy[0][b][i0 + ii][j0 + jj][0];
            float a0 = 0.f, a1 = 0.f, a2 = 0.f, a3 = 0.f;
#pragma unroll 8
            for (int f = 0; f < Fc; f++) {
                float hv = h[f];
                float4 w = *(const float4*)(Wp + f * Hc);
                a0 += hv * w.x; a1 += hv * w.y; a2 += hv * w.z; a3 += hv * w.w;
            }
            P[c * H2 + k0 + 0] = a0 + bv.x;
            P[c * H2 + k0 + 1] = a1 + bv.y;
            P[c * H2 + k0 + 2] = a2 + bv.z;
            P[c * H2 + k0 + 3] = a3 + bv.w;
        }
    }
    __syncthreads();

    const int slb = slen[b], tlb = tlen[b];
    const int g2  = t >> 6;        // cell-pair group: 0..3
    const int kh  = t & 63;        // output-pair index
    const int k0  = kh * 2;        // 0..126
    const bool isx = (kh < 32);    // first 64 outputs = hx, last 64 = hy
    const int kb  = isx ? k0 : (k0 - Hc);
    const float2* W2 = (const float2*)Wsh;

#define STORE_CELL(ci, jji, rx, ry) do {                                        \
        int gi = i0 + (ci), gj = j0 + (jji);                                    \
        float* hp = isx ? &HX[cur * 512 + (ci) * 64 + kb]                       \
                        : &HY[cur * 512 + (ci) * 64 + kb];                      \
        hp[0] = (rx); hp[1] = (ry);                                             \
        float* sp = isx ? &g_hx[depth][b][gi][gj][kb]                           \
                        : &g_hy[depth][b][gi][gj][kb];                          \
        sp[0] = (rx); sp[1] = (ry);                                             \
        bool m = (gi < slb) && (gj < tlb);                                      \
        int v = isx ? 0 : 1;                                                    \
        float* op = out + ((((size_t)(v * 2 + depth) * Bc + b) * Sc + gi) * Tc  \
                           + gj) * Hc + kb;                                     \
        op[0] = m ? (rx) : 0.f; op[1] = m ? (ry) : 0.f;                         \
    } while (0)

    for (int dd = 0; dd < 2 * TILE - 1; dd++) {
        int iilo = dd - (TILE - 1); if (iilo < 0) iilo = 0;
        int iihi = (dd < TILE - 1) ? dd : (TILE - 1);
        int cur = dd & 1, prv = cur ^ 1;

        int c0 = iilo + 2 * g2, c1 = c0 + 1;
        bool a0 = (c0 <= iihi), a1 = (c1 <= iihi);
        int jjc0 = dd - c0, jjc1 = dd - c1;

        const float* pa0 = a0 ? ((c0 > 0)   ? &HX[prv * 512 + (c0 - 1) * 64] : &HXtop[jjc0 * 64]) : HXtop;
        const float* pb0 = a0 ? ((jjc0 > 0) ? &HY[prv * 512 + c0 * 64]       : &HYleft[c0 * 64])  : HYleft;
        const float* pa1 = a1 ? ((c1 > 0)   ? &HX[prv * 512 + (c1 - 1) * 64] : &HXtop[jjc1 * 64]) : HXtop;
        const float* pb1 = a1 ? ((jjc1 > 0) ? &HY[prv * 512 + c1 * 64]       : &HYleft[c1 * 64])  : HYleft;

        // P is indexed by CELL (ii*TILE + jj), not by diagonal row index.
        int pcell0 = a0 ? (c0 * TILE + jjc0) : 0;
        int pcell1 = a1 ? (c1 * TILE + jjc1) : 0;

        float acc0x = P[pcell0 * H2 + k0], acc0y = P[pcell0 * H2 + k0 + 1];
        float acc1x = P[pcell1 * H2 + k0], acc1y = P[pcell1 * H2 + k0 + 1];

#pragma unroll 8
        for (int kk = 0; kk < Hc; kk++) {           // hx_above half of h_prev
            float2 w = W2[kk * 64 + kh];
            float h0 = pa0[kk], h1 = pa1[kk];
            acc0x += h0 * w.x; acc0y += h0 * w.y;
            acc1x += h1 * w.x; acc1y += h1 * w.y;
        }
#pragma unroll 8
        for (int kk = 0; kk < Hc; kk++) {           // hy_left half of h_prev
            float2 w = W2[(Hc + kk) * 64 + kh];
            float h0 = pb0[kk], h1 = pb1[kk];
            acc0x += h0 * w.x; acc0y += h0 * w.y;
            acc1x += h1 * w.x; acc1y += h1 * w.y;
        }

        if (a0) { float rx = tanhf(acc0x), ry = tanhf(acc0y); STORE_CELL(c0, jjc0, rx, ry); }
        if (a1) { float rx = tanhf(acc1x), ry = tanhf(acc1y); STORE_CELL(c1, jjc1, rx, ry); }
        __syncthreads();
    }
#undef STORE_CELL
}

// ---------------------------------------------------------------------------
static inline int diag_count(int d) {
    int lo2 = d - (TG - 1); if (lo2 < 0) lo2 = 0;
    int hi2 = (d < TG - 1) ? d : (TG - 1);
    return hi2 - lo2 + 1;
}

extern "C" void kernel_launch(void* const* d_in, const int* in_sizes, int n_in,
                              void* d_out, int out_size)
{
    const float* src = (const float*)d_in[0];
    const float* trg = (const float*)d_in[1];
    const float* Wix = (const float*)d_in[2];
    const float* Whx = (const float*)d_in[3];
    const float* bx  = (const float*)d_in[4];
    const float* Wiy = (const float*)d_in[5];
    const float* Why = (const float*)d_in[6];
    const float* by  = (const float*)d_in[7];
    const int*   slen = (const int*)d_in[8];
    const int*   tlen = (const int*)d_in[9];
    float* out = (float*)d_out;

    cudaFuncSetAttribute(wave_kernel,
                         cudaFuncAttributeMaxDynamicSharedMemorySize, SMEM_BYTES);

    proj0_kernel<<<Bc * (Sc + Tc), 64>>>(src, trg, Wix, Wiy);

    // Combined wavefront: step s runs depth-0 tiles on tile-diagonal s and
    // depth-1 tiles on tile-diagonal s-1 (pipelined one step behind).
    for (int s = 0; s <= NDIAG; s++) {
        int n0 = (s < NDIAG) ? diag_count(s) : 0;
        int n1 = (s >= 1) ? diag_count(s - 1) : 0;
        int blocks = (n0 + n1) * Bc;
        if (blocks == 0) continue;
        wave_kernel<<<blocks, 256, SMEM_BYTES>>>(
            Whx, Why, bx, by, Wix, Wiy, slen, tlen, out, s, n0);
    }
}

// round 3
// speedup vs baseline: 1.0350x; 1.0350x over previous
#include <cuda_runtime.h>
#include <math.h>

#define Bc 8
#define Sc 96
#define Tc 96
#define Fc 64
#define Hc 64
#define H2 128
#define TILE 8
#define TG 12       // 96 / TILE
#define NDIAG 23    // 2*TG - 1
#define NTHREADS 512

// Unmasked recurrence state (scratch): halos + depth-1 projections read this.
__device__ float g_hx[2][Bc][Sc][Tc][Hc];
__device__ float g_hy[2][Bc][Sc][Tc][Hc];
// Depth-0 input projections: px depends only on (b,i), py only on (b,j).
__device__ float g_px0[Bc][Sc][Hc];
__device__ float g_py0[Bc][Tc][Hc];

__device__ __forceinline__ float ftanh(float x) {
    float e = __expf(-2.0f * fabsf(x));
    float r = __fdividef(1.0f - e, 1.0f + e);
    return copysignf(r, x);
}

// ---------------------------------------------------------------------------
// Depth-0 projections: g_px0[b][i][:] = src[b,i,:] @ Wi_x[0];  g_py0 likewise.
// ---------------------------------------------------------------------------
__global__ void proj0_kernel(const float* __restrict__ src,
                             const float* __restrict__ trg,
                             const float* __restrict__ Wix,
                             const float* __restrict__ Wiy)
{
    __shared__ float row[Fc];
    const int r = blockIdx.x;
    const int k = threadIdx.x;
    const float* W;
    const float* inrow;
    float* outp;
    if (r < Bc * Sc) {
        inrow = src + r * Fc;  W = Wix;  outp = &g_px0[0][0][0] + r * Hc;
    } else {
        int rr = r - Bc * Sc;
        inrow = trg + rr * Fc; W = Wiy;  outp = &g_py0[0][0][0] + rr * Hc;
    }
    row[k] = inrow[k];
    __syncthreads();
    float acc = 0.f;
#pragma unroll 8
    for (int f = 0; f < Fc; f++) acc += row[f] * W[f * Hc + k];
    outp[k] = acc;
}

// ---------------------------------------------------------------------------
// Wavefront tile kernel. One CTA = one (depth, tile, batch). 512 threads =
// 64 output-pairs x 8 K-slices. Recurrence weights live in registers
// (16 rows x 2 cols per thread); partial dots reduced via butterfly shuffles.
// ---------------------------------------------------------------------------
// smem: P[64][128] + HX[2][8][64] + HY[2][8][64] + HXtop[8][64] + HYleft[8][64]
//       + stage (Wcat[64][128] | H0X[64][64] | H0Y[64][64])
#define SMEM_FLOATS (8192 + 1024 + 1024 + 512 + 512 + 16384)
#define SMEM_BYTES  (SMEM_FLOATS * 4)

__global__ void __launch_bounds__(NTHREADS, 2) wave_kernel(
    const float* __restrict__ Whx, const float* __restrict__ Why,
    const float* __restrict__ bx,  const float* __restrict__ by,
    const float* __restrict__ Wix, const float* __restrict__ Wiy,
    const int*   __restrict__ slen, const int* __restrict__ tlen,
    float* __restrict__ out, int s, int n0)
{
    extern __shared__ float smem[];
    float* P      = smem;            // [64][128] cell-major input proj (+bias)
    float* HX     = P + 8192;        // [2][8][64] ping-pong hx along diagonal
    float* HY     = HX + 1024;       // [2][8][64]
    float* HXtop  = HY + 1024;       // [8][64] hx halo from tile above (per jj)
    float* HYleft = HXtop + 512;     // [8][64] hy halo from tile left  (per ii)
    float* STW    = HYleft + 512;    // [64][128] staged Wi (depth-1 only)
    float* H0X    = STW + 8192;      // [64][64]  staged hx0 (depth-1 only)
    float* H0Y    = H0X + 4096;      // [64][64]  staged hy0 (depth-1 only)

    const int t    = threadIdx.x;
    const int slot = blockIdx.x >> 3;
    const int b    = blockIdx.x & 7;

    int depth, diag, pos;
    if (slot < n0) { depth = 0; diag = s;     pos = slot; }
    else           { depth = 1; diag = s - 1; pos = slot - n0; }
    int lo = diag - (TG - 1); if (lo < 0) lo = 0;
    const int ti = lo + pos;
    const int tj = diag - ti;
    const int i0 = ti * TILE, j0 = tj * TILE;

    const float* bxd = bx + depth * Hc;
    const float* byd = by + depth * Hc;

    // ---- halos from neighbor tiles (unmasked scratch), zeros at border ----
    {
        int rr = t >> 6, k = t & 63;
        HXtop[t]  = (ti > 0) ? g_hx[depth][b][i0 - 1][j0 + rr][k] : 0.f;
        HYleft[t] = (tj > 0) ? g_hy[depth][b][i0 + rr][j0 - 1][k] : 0.f;
    }

    // ---- per-cell input projections P[cell][k] with bias folded in ----
    if (depth == 0) {
        for (int idx = t; idx < 64 * H2; idx += NTHREADS) {
            int c = idx >> 7, k = idx & 127;
            int ii = c >> 3, jj = c & 7;
            P[idx] = (k < Hc) ? g_px0[b][i0 + ii][k] + bxd[k]
                              : g_py0[b][j0 + jj][k - Hc] + byd[k - Hc];
        }
        __syncthreads();
    } else {
        // stage Wi (combined) and previous-depth h tiles into smem
        for (int idx = t; idx < 64 * H2; idx += NTHREADS) {
            int f = idx >> 7, k = idx & 127;
            STW[idx] = (k < Hc) ? Wix[Fc * Hc + f * Hc + k]
                                : Wiy[Fc * Hc + f * Hc + (k - Hc)];
        }
        for (int idx = t; idx < 64 * Fc; idx += NTHREADS) {
            int c = idx >> 6, f = idx & 63;
            int ii = c >> 3, jj = c & 7;
            H0X[idx] = g_hx[0][b][i0 + ii][j0 + jj][f];
            H0Y[idx] = g_hy[0][b][i0 + ii][j0 + jj][f];
        }
        __syncthreads();
        // P[c][k] = h0 @ Wi + bias ; thread: cell c = t>>3, 16 k's split as
        // k = (t&7)*4 + e4*32 + e (conflict-free float4 columns)
        {
            const int c   = t >> 3;
            const int kb4 = (t & 7) * 4;
            float4 acc[4] = {{0,0,0,0},{0,0,0,0},{0,0,0,0},{0,0,0,0}};
            const float* HrowX = H0X + c * Fc;
            const float* HrowY = H0Y + c * Fc;
#pragma unroll 4
            for (int f = 0; f < Fc; f++) {
                float hx0 = HrowX[f];
                float hy0 = HrowY[f];
                const float* wr = STW + f * H2 + kb4;
#pragma unroll
                for (int e4 = 0; e4 < 4; e4++) {
                    float4 w = *(const float4*)(wr + e4 * 32);
                    float hv = (kb4 + e4 * 32 < Hc) ? hx0 : hy0;
                    acc[e4].x += hv * w.x; acc[e4].y += hv * w.y;
                    acc[e4].z += hv * w.z; acc[e4].w += hv * w.w;
                }
            }
            __syncthreads();  // done reading STW/H0 before P overwrites? (P separate) -- ordering only for reuse safety
#pragma unroll
            for (int e4 = 0; e4 < 4; e4++) {
                int k = kb4 + e4 * 32;
                float4 bb;
                if (k < Hc) bb = *(const float4*)(bxd + k);
                else        bb = *(const float4*)(byd + (k - Hc));
                float4 v = acc[e4];
                v.x += bb.x; v.y += bb.y; v.z += bb.z; v.w += bb.w;
                *(float4*)(P + c * H2 + k) = v;
            }
        }
        __syncthreads();
    }

    // ---- load recurrence-weight slice into registers ----
    // t -> (warp=khhi, lane); lane = kq*4 + khlo ; kh = khhi*4 + khlo
    const int lane = t & 31;
    const int kq   = lane >> 2;          // 0..7 : K-slice
    const int kh   = ((t >> 5) << 2) | (lane & 3);  // 0..63 : output pair
    const int k0   = kh * 2;
    const bool isx = (kh < 32);
    const int  kb  = isx ? k0 : (k0 - Hc);
    const int  hofs = (kq & 3) * 16;

    float2 w[16];
    {
        const float* Wbase = isx ? (Whx + depth * H2 * Hc + k0)
                                 : (Why + depth * H2 * Hc + (k0 - Hc));
#pragma unroll
        for (int u = 0; u < 16; u++)
            w[u] = *(const float2*)(Wbase + (kq * 16 + u) * Hc);
    }

    const int slb = slen[b], tlb = tlen[b];

    // ---- intra-tile wavefront ----
    for (int dd = 0; dd < 2 * TILE - 1; dd++) {
        int iilo = dd - (TILE - 1); if (iilo < 0) iilo = 0;
        int iihi = (dd < TILE - 1) ? dd : (TILE - 1);
        int cur = dd & 1, prv = cur ^ 1;

#pragma unroll
        for (int half = 0; half < 2; half++) {
            float acc0[4], acc1[4];
#pragma unroll
            for (int q = 0; q < 4; q++) {
                int c = half * 4 + q;
                acc0[q] = 0.f; acc1[q] = 0.f;
                if (c >= iilo && c <= iihi) {
                    int jjc = dd - c;
                    const float* pa = (c > 0)   ? &HX[prv * 512 + (c - 1) * 64]
                                                : &HXtop[jjc * 64];
                    const float* pb = (jjc > 0) ? &HY[prv * 512 + c * 64]
                                                : &HYleft[c * 64];
                    const float* hs = ((kq < 4) ? pa : pb) + hofs;
                    float a0 = 0.f, a1 = 0.f;
#pragma unroll
                    for (int u4 = 0; u4 < 4; u4++) {
                        float4 hv = *(const float4*)(hs + u4 * 4);
                        a0 += hv.x * w[u4*4+0].x; a1 += hv.x * w[u4*4+0].y;
                        a0 += hv.y * w[u4*4+1].x; a1 += hv.y * w[u4*4+1].y;
                        a0 += hv.z * w[u4*4+2].x; a1 += hv.z * w[u4*4+2].y;
                        a0 += hv.w * w[u4*4+3].x; a1 += hv.w * w[u4*4+3].y;
                    }
                    acc0[q] = a0; acc1[q] = a1;
                }
            }
#pragma unroll
            for (int q = 0; q < 4; q++) {
                int c = half * 4 + q;
                if (c >= iilo && c <= iihi) {   // uniform branch
                    float a0 = acc0[q], a1 = acc1[q];
                    a0 += __shfl_xor_sync(0xffffffffu, a0, 4);
                    a1 += __shfl_xor_sync(0xffffffffu, a1, 4);
                    a0 += __shfl_xor_sync(0xffffffffu, a0, 8);
                    a1 += __shfl_xor_sync(0xffffffffu, a1, 8);
                    a0 += __shfl_xor_sync(0xffffffffu, a0, 16);
                    a1 += __shfl_xor_sync(0xffffffffu, a1, 16);
                    if (kq == 0) {
                        int jjc = dd - c;
                        const float* pp = P + (c * TILE + jjc) * H2 + k0;
                        float rx = ftanh(pp[0] + a0);
                        float ry = ftanh(pp[1] + a1);
                        int gi = i0 + c, gj = j0 + jjc;
                        float2 v = make_float2(rx, ry);
                        // smem ping-pong for next diagonal
                        float* hp = (isx ? HX : HY) + cur * 512 + c * 64 + kb;
                        *(float2*)hp = v;
                        // global scratch (halos / depth-1 projections)
                        float* sp = isx ? &g_hx[depth][b][gi][gj][kb]
                                        : &g_hy[depth][b][gi][gj][kb];
                        *(float2*)sp = v;
                        // masked output
                        bool m = (gi < slb) && (gj < tlb);
                        int vsel = isx ? 0 : 1;
                        float* op = out + ((((size_t)(vsel * 2 + depth) * Bc + b)
                                           * Sc + gi) * Tc + gj) * Hc + kb;
                        float2 mv = m ? v : make_float2(0.f, 0.f);
                        *(float2*)op = mv;
                    }
                }
            }
        }
        __syncthreads();
    }
}

// ---------------------------------------------------------------------------
static inline int diag_count(int d) {
    int lo2 = d - (TG - 1); if (lo2 < 0) lo2 = 0;
    int hi2 = (d < TG - 1) ? d : (TG - 1);
    return hi2 - lo2 + 1;
}

extern "C" void kernel_launch(void* const* d_in, const int* in_sizes, int n_in,
                              void* d_out, int out_size)
{
    const float* src = (const float*)d_in[0];
    const float* trg = (const float*)d_in[1];
    const float* Wix = (const float*)d_in[2];
    const float* Whx = (const float*)d_in[3];
    const float* bx  = (const float*)d_in[4];
    const float* Wiy = (const float*)d_in[5];
    const float* Why = (const float*)d_in[6];
    const float* by  = (const float*)d_in[7];
    const int*   slen = (const int*)d_in[8];
    const int*   tlen = (const int*)d_in[9];
    float* out = (float*)d_out;

    cudaFuncSetAttribute(wave_kernel,
                         cudaFuncAttributeMaxDynamicSharedMemorySize, SMEM_BYTES);

    proj0_kernel<<<Bc * (Sc + Tc), 64>>>(src, trg, Wix, Wiy);

    // Combined wavefront: step s runs depth-0 tiles on tile-diagonal s and
    // depth-1 tiles on tile-diagonal s-1 (pipelined one step behind).
    for (int s = 0; s <= NDIAG; s++) {
        int n0 = (s < NDIAG) ? diag_count(s) : 0;
        int n1 = (s >= 1) ? diag_count(s - 1) : 0;
        int blocks = (n0 + n1) * Bc;
        if (blocks == 0) continue;
        wave_kernel<<<blocks, NTHREADS, SMEM_BYTES>>>(
            Whx, Why, bx, by, Wix, Wiy, slen, tlen, out, s, n0);
    }
}